// round 9
// baseline (speedup 1.0000x reference)
#include <cuda_runtime.h>
#include <cuda_fp16.h>
#include <cstdint>

// ============================================================================
// x (64,112,112,64) f32 NHWC; kernels (3,3,64,64) f32 HWIO (+-1); beta (64).
// out = conv3x3_SAME(BN_train(x), kernels), fp32.
//
// BN folded into GEMM: out = conv(fp16(x_raw), w*s_ci) + bias_co; padded
// border = fp16(-shift/scale). Implicit GEMM mma.sync.m16n8k16.f16.
// Persistent CTAs, 8 warps, warp-PRIVATE tile 16 pixels x 64 couts (round-5
// champion config), upgraded to a 3-stage cp.async pipeline (distance 2) and
// XOR-swizzled B (128B pitch, no padding) to fund the third A buffer.
// ============================================================================

#define N_  64
#define H_  112
#define W_  112
#define C_  64
#define HP  114
#define WP  114
#define M_CNT (N_*H_*W_)
#define NVEC  ((size_t)M_CNT * 16)
#define NPIX  (N_*H_*W_)
#define NTILES (NPIX/128)            // 6272
#define HW_   (H_*W_)                // 12544
#define PIXB  (C_*2)                 // 128 B per padded pixel
#define ROWB  (WP*PIXB)              // 14592 B per padded row

// B: [3 dy][192 k][64 co] fp16, 128B rows, XOR swizzle (k&7)<<4
#define BROWB  128
#define BCHUNKB (192*BROWB)          // 24576
#define B_BYTES (3*BCHUNKB)          // 73728

// A: per-warp [16 pixels][192 k] fp16, pitch 400B, TRIPLE buffered
#define APITCH 400
#define AWBUF  (16*APITCH)           // 6400
#define SM_A0  B_BYTES
#define CONV_SMEM (B_BYTES + 8*3*AWBUF)   // 227328

// ---------------- persistent device scratch (zero-init .bss) ----------------
__device__ __align__(16) unsigned short g_xf[(size_t)N_ * HP * WP * C_];
__device__ __align__(16) unsigned short g_wb[3 * 192 * 64];
__device__ float g_sum[C_];
__device__ float g_sumsq[C_];
__device__ float g_scale[C_];
__device__ float g_shift[C_];
__device__ float g_bias[C_];
__device__ unsigned short g_bord[C_];

// ============================ PTX helpers ===================================
__device__ __forceinline__ uint32_t smem_to_u32(const void* p) {
    uint32_t a;
    asm("{ .reg .u64 t; cvta.to.shared.u64 t, %1; cvt.u32.u64 %0, t; }"
        : "=r"(a) : "l"(p));
    return a;
}

#define LDSM_X4(r, addr) \
    asm volatile("ldmatrix.sync.aligned.m8n8.x4.shared.b16 {%0,%1,%2,%3}, [%4];" \
        : "=r"((r)[0]), "=r"((r)[1]), "=r"((r)[2]), "=r"((r)[3]) : "r"(addr))

#define LDSM_X4_T(r, addr) \
    asm volatile("ldmatrix.sync.aligned.m8n8.x4.trans.shared.b16 {%0,%1,%2,%3}, [%4];" \
        : "=r"((r)[0]), "=r"((r)[1]), "=r"((r)[2]), "=r"((r)[3]) : "r"(addr))

#define MMA16816(c, a, b0v, b1v) \
    asm volatile("mma.sync.aligned.m16n8k16.row.col.f32.f16.f16.f32 " \
        "{%0,%1,%2,%3}, {%4,%5,%6,%7}, {%8,%9}, {%0,%1,%2,%3};" \
        : "+f"((c)[0]), "+f"((c)[1]), "+f"((c)[2]), "+f"((c)[3]) \
        : "r"((a)[0]), "r"((a)[1]), "r"((a)[2]), "r"((a)[3]), \
          "r"(b0v), "r"(b1v))

#define CP_ASYNC16(dst_s, src_g) \
    asm volatile("cp.async.cg.shared.global [%0], [%1], 16;" \
        :: "r"(dst_s), "l"(src_g))
#define CP_COMMIT() asm volatile("cp.async.commit_group;" ::: "memory")
#define CP_WAIT2()  asm volatile("cp.async.wait_group 2;" ::: "memory")

__device__ __forceinline__ unsigned short f2h(float f) {
    __half h = __float2half_rn(f);
    return *reinterpret_cast<unsigned short*>(&h);
}

// ---------------------------------------------------------------------------
__global__ void k_zero_stats() {
    int i = threadIdx.x;
    if (i < C_) { g_sum[i] = 0.0f; g_sumsq[i] = 0.0f; }
}

// ---------------------------------------------------------------------------
// Fused: per-channel moments + raw-x fp16 conversion into padded buffer.
__global__ void __launch_bounds__(256) k_stats_conv(const float* __restrict__ x) {
    __shared__ float ssum[C_];
    __shared__ float ssq[C_];
    int tid = threadIdx.x;
    if (tid < C_) { ssum[tid] = 0.0f; ssq[tid] = 0.0f; }
    __syncthreads();

    const float4* xv = (const float4*)x;
    uint2* of = (uint2*)g_xf;
    int g = tid & 15;
    float4 s = make_float4(0.f, 0.f, 0.f, 0.f);
    float4 q = make_float4(0.f, 0.f, 0.f, 0.f);
    size_t stride = (size_t)gridDim.x * blockDim.x;
    for (size_t i = (size_t)blockIdx.x * blockDim.x + tid; i < NVEC; i += stride) {
        float4 v = xv[i];
        s.x += v.x; s.y += v.y; s.z += v.z; s.w += v.w;
        q.x += v.x * v.x; q.y += v.y * v.y; q.z += v.z * v.z; q.w += v.w * v.w;

        size_t pix = i >> 4;
        int n   = (int)(pix / HW_);
        int rem = (int)(pix % HW_);
        int h   = rem / W_;
        int w   = rem % W_;
        unsigned short h0 = f2h(v.x), h1 = f2h(v.y), h2 = f2h(v.z), h3 = f2h(v.w);
        size_t dpix = ((size_t)n * HP + (h + 1)) * WP + (w + 1);
        of[dpix * 16 + g] = make_uint2((uint32_t)h0 | ((uint32_t)h1 << 16),
                                       (uint32_t)h2 | ((uint32_t)h3 << 16));
    }
    atomicAdd(&ssum[g * 4 + 0], s.x); atomicAdd(&ssq[g * 4 + 0], q.x);
    atomicAdd(&ssum[g * 4 + 1], s.y); atomicAdd(&ssq[g * 4 + 1], q.y);
    atomicAdd(&ssum[g * 4 + 2], s.z); atomicAdd(&ssq[g * 4 + 2], q.z);
    atomicAdd(&ssum[g * 4 + 3], s.w); atomicAdd(&ssq[g * 4 + 3], q.w);
    __syncthreads();
    if (tid < C_) {
        atomicAdd(&g_sum[tid],   ssum[tid]);
        atomicAdd(&g_sumsq[tid], ssq[tid]);
    }
}

// ---------------------------------------------------------------------------
// Fused finalize + bias (single block, 64 threads).
__global__ void k_finprep(const float* __restrict__ beta, const float* __restrict__ kw) {
    int c = threadIdx.x;
    if (c < C_) {
        const float inv_m = 1.0f / (float)M_CNT;
        float m = g_sum[c] * inv_m;
        float v = g_sumsq[c] * inv_m - m * m;
        float s = rsqrtf(v + 1e-5f);
        float sh = beta[c] - m * s;
        g_scale[c] = s;
        g_shift[c] = sh;
        g_bord[c]  = f2h(-sh / s);
    }
    __syncthreads();
    if (c < C_) {
        float acc = 0.0f;
        for (int t = 0; t < 9; t++)
            for (int ci = 0; ci < 64; ci++)
                acc += kw[((size_t)t * 64 + ci) * 64 + c] * g_shift[ci];
        g_bias[c] = acc;
    }
}

// ---------------------------------------------------------------------------
// Fused wprep (swizzled B image) + border fill.
__global__ void __launch_bounds__(256) k_bw(const float* __restrict__ kw) {
    int i = blockIdx.x * blockDim.x + threadIdx.x;
    if (i < 36864) {
        int cout = i & 63;
        int cin  = (i >> 6) & 63;
        int t    = i >> 12;            // dy*3+dx
        int dy = t / 3, dx = t % 3;
        float v = kw[((size_t)t * 64 + cin) * 64 + cout] * g_scale[cin];
        int k = dx * 64 + cin;
        int off = k * BROWB + cout * 2;
        off ^= (k & 7) << 4;                       // XOR swizzle
        *(unsigned short*)((char*)g_wb + (size_t)dy * BCHUNKB + off) = f2h(v);
        return;
    }
    int idx = i - 36864;
    if (idx >= 64 * 452 * 16) return;
    int g   = idx & 15;
    int bp  = (idx >> 4) % 452;
    int img = (idx >> 4) / 452;
    int h, w;
    if (bp < 114)      { h = 0;   w = bp; }
    else if (bp < 228) { h = 113; w = bp - 114; }
    else { int j = bp - 228; h = 1 + (j >> 1); w = (j & 1) ? 113 : 0; }
    const unsigned short* bd = g_bord;
    uint32_t v0 = (uint32_t)bd[g*4+0] | ((uint32_t)bd[g*4+1] << 16);
    uint32_t v1 = (uint32_t)bd[g*4+2] | ((uint32_t)bd[g*4+3] << 16);
    ((uint2*)g_xf)[(((size_t)img * HP + h) * WP + w) * 16 + g] = make_uint2(v0, v1);
}

// ---------------------------------------------------------------------------
// Conv: persistent CTAs, 256 thr = 8 warps, warp-PRIVATE tile 16 pix x 64 co.
// 3-stage cp.async pipeline, prefetch distance 2, one commit per chunk.
__global__ void __launch_bounds__(256, 1)
k_conv(float* __restrict__ out) {
    extern __shared__ __align__(1024) unsigned char smem[];
    uint32_t sb = smem_to_u32(smem);
    int tid = threadIdx.x;

    // stage B once (73728 B, already swizzled in gmem image)
    {
        const uint4* src = (const uint4*)g_wb;
        uint4* dst = (uint4*)smem;
        for (int i = tid; i < B_BYTES / 16; i += 256) dst[i] = src[i];
    }
    __syncthreads();

    int lane = tid & 31;
    int wid  = tid >> 5;           // warp 0..7 -> pixels wid*16..+16
    int sel  = lane >> 3;
    int l7   = lane & 7;

    uint32_t awbase = sb + SM_A0 + (uint32_t)wid * (3 * AWBUF);
    uint32_t a_off  = (uint32_t)(((sel & 1) * 8 + l7) * APITCH + (sel >> 1) * 16);

    // B per-lane: row part + 4 swizzled cout-block offsets
    uint32_t b_row = sb + (uint32_t)(((sel & 1) * 8 + l7) * BROWB);
    uint32_t bo[4];
    #pragma unroll
    for (int nf = 0; nf < 4; nf++)
        bo[nf] = (uint32_t)((((sel >> 1) * 16) + nf * 32) ^ (l7 << 4));

    // staging: lane -> pixel (lane>>1), half (lane&1), 12 x 16B
    uint32_t dst_off = (uint32_t)((lane >> 1) * APITCH + (lane & 1) * 192);
    const char* gx = (const char*)g_xf;

    int cq = lane & 3;
    float bia0[8], bia1[8];
    #pragma unroll
    for (int nf = 0; nf < 8; nf++) {
        bia0[nf] = g_bias[nf * 8 + 2 * cq];
        bia1[nf] = g_bias[nf * 8 + 2 * cq + 1];
    }

    // prologue: prefetch chunks 0 (tile0,dy0) and 1 (tile0,dy1)
    {
        int gp  = blockIdx.x * 128 + wid * 16 + (lane >> 1);
        int n   = gp / HW_;
        int rem = gp % HW_;
        int h   = rem / W_;
        int w   = rem % W_;
        const char* src = gx + (((size_t)n * HP + h) * WP + w) * PIXB + (lane & 1) * 192;
        #pragma unroll
        for (int i = 0; i < 12; i++) CP_ASYNC16(awbase + dst_off + i * 16, src + i * 16);
        CP_COMMIT();
        src += ROWB;
        #pragma unroll
        for (int i = 0; i < 12; i++) CP_ASYNC16(awbase + AWBUF + dst_off + i * 16, src + i * 16);
        CP_COMMIT();
    }

    int bi = 0;    // buffer of current chunk
    for (int tile = blockIdx.x; tile < NTILES; tile += gridDim.x) {
        // base of this tile (dy=0) and of the next tile
        int gp  = tile * 128 + wid * 16 + (lane >> 1);
        int n   = gp / HW_;
        int rem = gp % HW_;
        int h   = rem / W_;
        int w   = rem % W_;
        const char* base = gx + (((size_t)n * HP + h) * WP + w) * PIXB + (lane & 1) * 192;

        int t2 = tile + gridDim.x;
        const char* base2 = nullptr;
        if (t2 < NTILES) {
            int gp2  = t2 * 128 + wid * 16 + (lane >> 1);
            int n2   = gp2 / HW_;
            int rem2 = gp2 % HW_;
            int h2   = rem2 / W_;
            int w2   = rem2 % W_;
            base2 = gx + (((size_t)n2 * HP + h2) * WP + w2) * PIXB + (lane & 1) * 192;
        }

        float c[32];
        #pragma unroll
        for (int i = 0; i < 32; i++) c[i] = 0.0f;

        #pragma unroll 1
        for (int j = 0; j < 3; j++) {
            // prefetch chunk j+2 into buffer (bi+2)%3; always commit one group
            int nb = (bi == 0) ? 2 : bi - 1;     // (bi+2)%3
            const char* src = nullptr;
            if (j == 0)            src = base + 2 * ROWB;
            else if (base2)        src = base2 + (size_t)(j - 1) * ROWB;
            if (src) {
                uint32_t d = awbase + (uint32_t)nb * AWBUF + dst_off;
                #pragma unroll
                for (int i = 0; i < 12; i++) CP_ASYNC16(d + i * 16, src + i * 16);
            }
            CP_COMMIT();
            CP_WAIT2();
            __syncwarp();

            uint32_t Abase = awbase + (uint32_t)bi * AWBUF + a_off;
            uint32_t Bbase = b_row + (uint32_t)j * BCHUNKB;

            #pragma unroll
            for (int s = 0; s < 12; s++) {
                uint32_t ra[4], rb0[4], rb1[4], rb2[4], rb3[4];
                LDSM_X4(ra, Abase + s * 32);
                uint32_t Bs = Bbase + (uint32_t)s * (16 * BROWB);
                LDSM_X4_T(rb0, Bs + bo[0]);
                LDSM_X4_T(rb1, Bs + bo[1]);
                LDSM_X4_T(rb2, Bs + bo[2]);
                LDSM_X4_T(rb3, Bs + bo[3]);

                MMA16816(c +  0, ra, rb0[0], rb0[1]);
                MMA16816(c +  4, ra, rb0[2], rb0[3]);
                MMA16816(c +  8, ra, rb1[0], rb1[1]);
                MMA16816(c + 12, ra, rb1[2], rb1[3]);
                MMA16816(c + 16, ra, rb2[0], rb2[1]);
                MMA16816(c + 20, ra, rb2[2], rb2[3]);
                MMA16816(c + 24, ra, rb3[0], rb3[1]);
                MMA16816(c + 28, ra, rb3[2], rb3[3]);
            }
            bi = (bi == 2) ? 0 : bi + 1;
        }

        // epilogue: add bias, store 16 pixels x 64 couts
        int r = lane >> 2;
        int pix0 = tile * 128 + wid * 16 + r;
        float* o0 = out + (size_t)pix0 * 64 + 2 * cq;
        float* o1 = o0 + 8 * 64;
        #pragma unroll
        for (int nf = 0; nf < 8; nf++) {
            *(float2*)(o0 + nf * 8) = make_float2(c[nf*4 + 0] + bia0[nf],
                                                  c[nf*4 + 1] + bia1[nf]);
            *(float2*)(o1 + nf * 8) = make_float2(c[nf*4 + 2] + bia0[nf],
                                                  c[nf*4 + 3] + bia1[nf]);
        }
    }
}

// ---------------------------------------------------------------------------
extern "C" void kernel_launch(void* const* d_in, const int* in_sizes, int n_in,
                              void* d_out, int out_size) {
    const float* x    = (const float*)d_in[0];
    const float* kw   = (const float*)d_in[1];
    const float* beta = (const float*)d_in[2];
    float* out = (float*)d_out;
    (void)in_sizes; (void)n_in; (void)out_size;

    cudaFuncSetAttribute(k_conv, cudaFuncAttributeMaxDynamicSharedMemorySize, CONV_SMEM);

    k_zero_stats<<<1, 64>>>();
    k_stats_conv<<<2048, 256>>>(x);
    k_finprep<<<1, 64>>>(beta, kw);
    k_bw<<<(36864 + 64 * 452 * 16 + 255) / 256, 256>>>(kw);
    k_conv<<<152, 256, CONV_SMEM>>>(out);
}

// round 10
// speedup vs baseline: 1.0002x; 1.0002x over previous
#include <cuda_runtime.h>
#include <cuda_fp16.h>
#include <cstdint>

// ============================================================================
// x (64,112,112,64) f32 NHWC; kernels (3,3,64,64) f32 HWIO (+-1); beta (64).
// out = conv3x3_SAME(BN_train(x), kernels), fp32.
//
// BN folded into GEMM: out = conv(fp16(x_raw), w*s_ci) + bias_co; padded
// border = fp16(-shift/scale). Implicit GEMM mma.sync.m16n8k16.f16.
// Conv = round-5 champion config: persistent CTAs, 8 warps, warp-PRIVATE
// tile 16 pixels x 64 couts, cp.async double buffer, wait_group 1, syncwarp.
// Launch order puts k_conv at index 3 (the ncu-captured slot).
// ============================================================================

#define N_  64
#define H_  112
#define W_  112
#define C_  64
#define HP  114
#define WP  114
#define M_CNT (N_*H_*W_)
#define NVEC  ((size_t)M_CNT * 16)
#define NPIX  (N_*H_*W_)
#define NTILES (NPIX/128)            // 6272
#define HW_   (H_*W_)                // 12544
#define PIXB  (C_*2)                 // 128 B per padded pixel
#define ROWB  (WP*PIXB)              // 14592 B per padded row
#define SBLK  1024                   // stats blocks

// B: [3 dy][192 k][72 pitch] fp16
#define BPITCH 72
#define BROWB  (BPITCH*2)            // 144
#define BCHUNKB (192*BROWB)          // 27648
#define B_BYTES (3*BCHUNKB)          // 82944

// A: per-warp [16 pixels][192 k] fp16, pitch 400B, double buffered
#define APITCH 400
#define AWBUF  (16*APITCH)           // 6400
#define SM_A0  B_BYTES
#define CONV_SMEM (B_BYTES + 8*2*AWBUF)   // 185344

// ---------------- persistent device scratch (zero-init .bss) ----------------
__device__ __align__(16) unsigned short g_xf[(size_t)N_ * HP * WP * C_];
__device__ __align__(16) unsigned short g_wb[3 * 192 * BPITCH];
__device__ float g_psum[SBLK * C_];
__device__ float g_psq[SBLK * C_];
__device__ float g_scale[C_];
__device__ float g_shift[C_];
__device__ float g_bias[C_];
__device__ unsigned short g_bord[C_];

// ============================ PTX helpers ===================================
__device__ __forceinline__ uint32_t smem_to_u32(const void* p) {
    uint32_t a;
    asm("{ .reg .u64 t; cvta.to.shared.u64 t, %1; cvt.u32.u64 %0, t; }"
        : "=r"(a) : "l"(p));
    return a;
}

#define LDSM_X4(r, addr) \
    asm volatile("ldmatrix.sync.aligned.m8n8.x4.shared.b16 {%0,%1,%2,%3}, [%4];" \
        : "=r"((r)[0]), "=r"((r)[1]), "=r"((r)[2]), "=r"((r)[3]) : "r"(addr))

#define LDSM_X4_T(r, addr) \
    asm volatile("ldmatrix.sync.aligned.m8n8.x4.trans.shared.b16 {%0,%1,%2,%3}, [%4];" \
        : "=r"((r)[0]), "=r"((r)[1]), "=r"((r)[2]), "=r"((r)[3]) : "r"(addr))

#define MMA16816(c, a, b0v, b1v) \
    asm volatile("mma.sync.aligned.m16n8k16.row.col.f32.f16.f16.f32 " \
        "{%0,%1,%2,%3}, {%4,%5,%6,%7}, {%8,%9}, {%0,%1,%2,%3};" \
        : "+f"((c)[0]), "+f"((c)[1]), "+f"((c)[2]), "+f"((c)[3]) \
        : "r"((a)[0]), "r"((a)[1]), "r"((a)[2]), "r"((a)[3]), \
          "r"(b0v), "r"(b1v))

#define CP_ASYNC16(dst_s, src_g) \
    asm volatile("cp.async.cg.shared.global [%0], [%1], 16;" \
        :: "r"(dst_s), "l"(src_g))
#define CP_COMMIT() asm volatile("cp.async.commit_group;" ::: "memory")
#define CP_WAIT0()  asm volatile("cp.async.wait_group 0;" ::: "memory")
#define CP_WAIT1()  asm volatile("cp.async.wait_group 1;" ::: "memory")

__device__ __forceinline__ unsigned short f2h(float f) {
    __half h = __float2half_rn(f);
    return *reinterpret_cast<unsigned short*>(&h);
}

// ---------------------------------------------------------------------------
// Launch 0: per-channel partial moments (per-block, atomic-free) + fp16 x.
__global__ void __launch_bounds__(256) k_stats_conv(const float* __restrict__ x) {
    __shared__ float ssum[C_];
    __shared__ float ssq[C_];
    int tid = threadIdx.x;
    if (tid < C_) { ssum[tid] = 0.0f; ssq[tid] = 0.0f; }
    __syncthreads();

    const float4* xv = (const float4*)x;
    uint2* of = (uint2*)g_xf;
    int g = tid & 15;
    float4 s = make_float4(0.f, 0.f, 0.f, 0.f);
    float4 q = make_float4(0.f, 0.f, 0.f, 0.f);
    size_t stride = (size_t)gridDim.x * blockDim.x;     // multiple of 16
    for (size_t i = (size_t)blockIdx.x * blockDim.x + tid; i < NVEC; i += stride) {
        float4 v = xv[i];
        s.x += v.x; s.y += v.y; s.z += v.z; s.w += v.w;
        q.x += v.x * v.x; q.y += v.y * v.y; q.z += v.z * v.z; q.w += v.w * v.w;

        size_t pix = i >> 4;
        int n   = (int)(pix / HW_);
        int rem = (int)(pix % HW_);
        int h   = rem / W_;
        int w   = rem % W_;
        unsigned short h0 = f2h(v.x), h1 = f2h(v.y), h2 = f2h(v.z), h3 = f2h(v.w);
        size_t dpix = ((size_t)n * HP + (h + 1)) * WP + (w + 1);
        of[dpix * 16 + g] = make_uint2((uint32_t)h0 | ((uint32_t)h1 << 16),
                                       (uint32_t)h2 | ((uint32_t)h3 << 16));
    }
    atomicAdd(&ssum[g * 4 + 0], s.x); atomicAdd(&ssq[g * 4 + 0], q.x);
    atomicAdd(&ssum[g * 4 + 1], s.y); atomicAdd(&ssq[g * 4 + 1], q.y);
    atomicAdd(&ssum[g * 4 + 2], s.z); atomicAdd(&ssq[g * 4 + 2], q.z);
    atomicAdd(&ssum[g * 4 + 3], s.w); atomicAdd(&ssq[g * 4 + 3], q.w);
    __syncthreads();
    if (tid < C_) {
        g_psum[blockIdx.x * C_ + tid] = ssum[tid];
        g_psq [blockIdx.x * C_ + tid] = ssq[tid];
    }
}

// ---------------------------------------------------------------------------
// Launch 1: reduce partials -> scale/shift/border + bias (one block).
__global__ void k_finprep(const float* __restrict__ beta, const float* __restrict__ kw) {
    int c = threadIdx.x;
    if (c < C_) {
        float s = 0.0f, q = 0.0f;
        for (int b = 0; b < SBLK; b++) {
            s += g_psum[b * C_ + c];
            q += g_psq [b * C_ + c];
        }
        const float inv_m = 1.0f / (float)M_CNT;
        float m  = s * inv_m;
        float v  = q * inv_m - m * m;
        float sc = rsqrtf(v + 1e-5f);
        float sh = beta[c] - m * sc;
        g_scale[c] = sc;
        g_shift[c] = sh;
        g_bord[c]  = f2h(-sh / sc);
    }
    __syncthreads();
    if (c < C_) {
        float acc = 0.0f;
        for (int t = 0; t < 9; t++)
            for (int ci = 0; ci < 64; ci++)
                acc += kw[((size_t)t * 64 + ci) * 64 + c] * g_shift[ci];
        g_bias[c] = acc;
    }
}

// ---------------------------------------------------------------------------
// Launch 2: B image (144B pitch) + border fill.
__global__ void __launch_bounds__(256) k_bw(const float* __restrict__ kw) {
    int i = blockIdx.x * blockDim.x + threadIdx.x;
    if (i < 36864) {
        int cout = i & 63;
        int cin  = (i >> 6) & 63;
        int t    = i >> 12;            // dy*3+dx
        int dy = t / 3, dx = t % 3;
        float v = kw[((size_t)t * 64 + cin) * 64 + cout] * g_scale[cin];
        g_wb[(size_t)dy * (192 * BPITCH) + (dx * 64 + cin) * BPITCH + cout] = f2h(v);
        return;
    }
    int idx = i - 36864;
    if (idx >= 64 * 452 * 16) return;
    int g   = idx & 15;
    int bp  = (idx >> 4) % 452;
    int img = (idx >> 4) / 452;
    int h, w;
    if (bp < 114)      { h = 0;   w = bp; }
    else if (bp < 228) { h = 113; w = bp - 114; }
    else { int j = bp - 228; h = 1 + (j >> 1); w = (j & 1) ? 113 : 0; }
    const unsigned short* bd = g_bord;
    uint32_t v0 = (uint32_t)bd[g*4+0] | ((uint32_t)bd[g*4+1] << 16);
    uint32_t v1 = (uint32_t)bd[g*4+2] | ((uint32_t)bd[g*4+3] << 16);
    ((uint2*)g_xf)[(((size_t)img * HP + h) * WP + w) * 16 + g] = make_uint2(v0, v1);
}

// ---------------------------------------------------------------------------
// Launch 3 (ncu-captured): conv. Round-5 champion config verbatim.
__global__ void __launch_bounds__(256, 1)
k_conv(float* __restrict__ out) {
    extern __shared__ __align__(1024) unsigned char smem[];
    uint32_t sb = smem_to_u32(smem);
    int tid = threadIdx.x;

    // stage B once
    {
        const uint4* src = (const uint4*)g_wb;
        uint4* dst = (uint4*)smem;
        for (int i = tid; i < B_BYTES / 16; i += 256) dst[i] = src[i];
    }
    __syncthreads();

    int lane = tid & 31;
    int wid  = tid >> 5;
    int sel  = lane >> 3;
    int l7   = lane & 7;

    uint32_t awbase = sb + SM_A0 + (uint32_t)wid * (2 * AWBUF);
    uint32_t a_off  = awbase + (uint32_t)(((sel & 1) * 8 + l7) * APITCH + (sel >> 1) * 16);
    uint32_t b_base = sb + (uint32_t)(((sel & 1) * 8 + l7) * BROWB + ((sel >> 1) * 8) * 2);

    int p_local = lane >> 1;       // 0..15
    int half    = lane & 1;
    uint32_t dst_off = (uint32_t)(p_local * APITCH + half * 192);
    const char* gx = (const char*)g_xf;

    int cq = lane & 3;
    float bia0[8], bia1[8];
    #pragma unroll
    for (int nsl = 0; nsl < 8; nsl++) {
        bia0[nsl] = g_bias[nsl * 8 + 2 * cq];
        bia1[nsl] = g_bias[nsl * 8 + 2 * cq + 1];
    }

    uint32_t jj = 0;               // free-running chunk counter (buffer parity)

    // prologue: prefetch (first tile, dy=0) into buf 0
    {
        int gp  = blockIdx.x * 128 + wid * 16 + p_local;
        int n   = gp / HW_;
        int rem = gp % HW_;
        int h   = rem / W_;
        int w   = rem % W_;
        const char* src = gx + (((size_t)n * HP + h) * WP + w) * PIXB + half * 192;
        uint32_t d = awbase + dst_off;
        #pragma unroll
        for (int i = 0; i < 12; i++) CP_ASYNC16(d + i * 16, src + i * 16);
        CP_COMMIT();
    }

    for (int tile = blockIdx.x; tile < NTILES; tile += gridDim.x) {
        int gp  = tile * 128 + wid * 16 + p_local;
        int n   = gp / HW_;
        int rem = gp % HW_;
        int h   = rem / W_;
        int w   = rem % W_;
        const char* base = gx + (((size_t)n * HP + h) * WP + w) * PIXB + half * 192;

        float c[32];
        #pragma unroll
        for (int i = 0; i < 32; i++) c[i] = 0.0f;

        #pragma unroll 1
        for (int j = 0; j < 3; j++) {
            uint32_t buf  = jj & 1;
            uint32_t nbuf = buf ^ 1;
            jj++;

            // prefetch next chunk (distance 1), then wait for current
            if (j < 2) {
                const char* src = base + (size_t)(j + 1) * ROWB;
                uint32_t d = awbase + nbuf * AWBUF + dst_off;
                #pragma unroll
                for (int i = 0; i < 12; i++) CP_ASYNC16(d + i * 16, src + i * 16);
                CP_COMMIT();
                CP_WAIT1();
            } else {
                int t2 = tile + gridDim.x;
                if (t2 < NTILES) {
                    int gp2  = t2 * 128 + wid * 16 + p_local;
                    int n2   = gp2 / HW_;
                    int rem2 = gp2 % HW_;
                    int h2   = rem2 / W_;
                    int w2   = rem2 % W_;
                    const char* src = gx + (((size_t)n2 * HP + h2) * WP + w2) * PIXB + half * 192;
                    uint32_t d = awbase + nbuf * AWBUF + dst_off;
                    #pragma unroll
                    for (int i = 0; i < 12; i++) CP_ASYNC16(d + i * 16, src + i * 16);
                    CP_COMMIT();
                    CP_WAIT1();
                } else {
                    CP_WAIT0();
                }
            }
            __syncwarp();

            uint32_t Abase = a_off + buf * AWBUF;
            uint32_t Bbase = b_base + j * BCHUNKB;

            #pragma unroll
            for (int s = 0; s < 12; s++) {
                uint32_t ra[4], rb0[4], rb1[4], rb2[4], rb3[4];
                LDSM_X4(ra, Abase + s * 32);
                uint32_t Bs = Bbase + s * (16 * BROWB);
                LDSM_X4_T(rb0, Bs);
                LDSM_X4_T(rb1, Bs + 32);
                LDSM_X4_T(rb2, Bs + 64);
                LDSM_X4_T(rb3, Bs + 96);

                MMA16816(c +  0, ra, rb0[0], rb0[1]);
                MMA16816(c +  4, ra, rb0[2], rb0[3]);
                MMA16816(c +  8, ra, rb1[0], rb1[1]);
                MMA16816(c + 12, ra, rb1[2], rb1[3]);
                MMA16816(c + 16, ra, rb2[0], rb2[1]);
                MMA16816(c + 20, ra, rb2[2], rb2[3]);
                MMA16816(c + 24, ra, rb3[0], rb3[1]);
                MMA16816(c + 28, ra, rb3[2], rb3[3]);
            }
        }

        // epilogue: add bias, store
        int r = lane >> 2;
        int pix0 = tile * 128 + wid * 16 + r;
        float* o0 = out + (size_t)pix0 * 64 + 2 * cq;
        float* o1 = o0 + 8 * 64;
        #pragma unroll
        for (int nsl = 0; nsl < 8; nsl++) {
            *(float2*)(o0 + nsl * 8) = make_float2(c[nsl*4 + 0] + bia0[nsl],
                                                   c[nsl*4 + 1] + bia1[nsl]);
            *(float2*)(o1 + nsl * 8) = make_float2(c[nsl*4 + 2] + bia0[nsl],
                                                   c[nsl*4 + 3] + bia1[nsl]);
        }
    }
}

// ---------------------------------------------------------------------------
extern "C" void kernel_launch(void* const* d_in, const int* in_sizes, int n_in,
                              void* d_out, int out_size) {
    const float* x    = (const float*)d_in[0];
    const float* kw   = (const float*)d_in[1];
    const float* beta = (const float*)d_in[2];
    float* out = (float*)d_out;
    (void)in_sizes; (void)n_in; (void)out_size;

    cudaFuncSetAttribute(k_conv, cudaFuncAttributeMaxDynamicSharedMemorySize, CONV_SMEM);

    k_stats_conv<<<SBLK, 256>>>(x);                              // launch 0
    k_finprep<<<1, 64>>>(beta, kw);                              // launch 1
    k_bw<<<(36864 + 64 * 452 * 16 + 255) / 256, 256>>>(kw);      // launch 2
    k_conv<<<152, 256, CONV_SMEM>>>(out);                        // launch 3 (profiled)
}

// round 11
// speedup vs baseline: 1.1258x; 1.1255x over previous
#include <cuda_runtime.h>
#include <cuda_fp16.h>
#include <cstdint>

// ============================================================================
// x (64,112,112,64) f32 NHWC; kernels (3,3,64,64) f32 HWIO (+-1); beta (64).
// out = conv3x3_SAME(BN_train(x), kernels), fp32.
//
// BN folded into GEMM: out = conv(fp16(x_raw), w*s_ci) + bias_co; padded
// border = fp16(-shift/scale). Implicit GEMM mma.sync.m16n8k16.f16.
// Conv: persistent CTAs, 512 thr = 16 warps = 8 pairs. Pair shares a
// 16-pixel A buffer (double buffered, cp.async); warp tile 16 px x 32 co.
// Occupancy 25% (4 warps/SMSP) to hide LDSM/MMA latency (R10 ncu showed
// tensor=35%, occ=12.5%, issue=11% -> latency-bound, not traffic-bound).
// ============================================================================

#define N_  64
#define H_  112
#define W_  112
#define C_  64
#define HP  114
#define WP  114
#define M_CNT (N_*H_*W_)
#define NVEC  ((size_t)M_CNT * 16)
#define NPIX  (N_*H_*W_)
#define NTILES (NPIX/128)            // 6272
#define HW_   (H_*W_)                // 12544
#define PIXB  (C_*2)                 // 128 B per padded pixel
#define ROWB  (WP*PIXB)              // 14592 B per padded row
#define SBLK  1024                   // stats blocks

// B: [3 dy][192 k][64 co] fp16, 128B rows, XOR swizzle (k&7)<<4  (R9-verified)
#define BROWB  128
#define BCHUNKB (192*BROWB)          // 24576
#define B_BYTES (3*BCHUNKB)          // 73728

// A: per-PAIR [16 pixels][192 k] fp16, pitch 400B, double buffered
#define APITCH 400
#define AWBUF  (16*APITCH)           // 6400
#define SM_A0  B_BYTES
#define CONV_SMEM (B_BYTES + 8*2*AWBUF)   // 176128

// ---------------- persistent device scratch (zero-init .bss) ----------------
__device__ __align__(16) unsigned short g_xf[(size_t)N_ * HP * WP * C_];
__device__ __align__(16) unsigned short g_wb[3 * 192 * 64];
__device__ float g_psum[SBLK * C_];
__device__ float g_psq[SBLK * C_];
__device__ float g_scale[C_];
__device__ float g_shift[C_];
__device__ float g_bias[C_];
__device__ unsigned short g_bord[C_];

// ============================ PTX helpers ===================================
__device__ __forceinline__ uint32_t smem_to_u32(const void* p) {
    uint32_t a;
    asm("{ .reg .u64 t; cvta.to.shared.u64 t, %1; cvt.u32.u64 %0, t; }"
        : "=r"(a) : "l"(p));
    return a;
}

#define LDSM_X4(r, addr) \
    asm volatile("ldmatrix.sync.aligned.m8n8.x4.shared.b16 {%0,%1,%2,%3}, [%4];" \
        : "=r"((r)[0]), "=r"((r)[1]), "=r"((r)[2]), "=r"((r)[3]) : "r"(addr))

#define LDSM_X4_T(r, addr) \
    asm volatile("ldmatrix.sync.aligned.m8n8.x4.trans.shared.b16 {%0,%1,%2,%3}, [%4];" \
        : "=r"((r)[0]), "=r"((r)[1]), "=r"((r)[2]), "=r"((r)[3]) : "r"(addr))

#define MMA16816(c, a, b0v, b1v) \
    asm volatile("mma.sync.aligned.m16n8k16.row.col.f32.f16.f16.f32 " \
        "{%0,%1,%2,%3}, {%4,%5,%6,%7}, {%8,%9}, {%0,%1,%2,%3};" \
        : "+f"((c)[0]), "+f"((c)[1]), "+f"((c)[2]), "+f"((c)[3]) \
        : "r"((a)[0]), "r"((a)[1]), "r"((a)[2]), "r"((a)[3]), \
          "r"(b0v), "r"(b1v))

#define CP_ASYNC16(dst_s, src_g) \
    asm volatile("cp.async.cg.shared.global [%0], [%1], 16;" \
        :: "r"(dst_s), "l"(src_g))
#define CP_COMMIT() asm volatile("cp.async.commit_group;" ::: "memory")
#define CP_WAIT0()  asm volatile("cp.async.wait_group 0;" ::: "memory")
#define BAR_SYNC(id) asm volatile("bar.sync %0, 64;" :: "r"(id) : "memory")

__device__ __forceinline__ unsigned short f2h(float f) {
    __half h = __float2half_rn(f);
    return *reinterpret_cast<unsigned short*>(&h);
}

// ---------------------------------------------------------------------------
// Launch 0: per-channel partial moments (per-block, no global atomics) + fp16 x.
__global__ void __launch_bounds__(256) k_stats_conv(const float* __restrict__ x) {
    __shared__ float ssum[C_];
    __shared__ float ssq[C_];
    int tid = threadIdx.x;
    if (tid < C_) { ssum[tid] = 0.0f; ssq[tid] = 0.0f; }
    __syncthreads();

    const float4* xv = (const float4*)x;
    uint2* of = (uint2*)g_xf;
    int g = tid & 15;
    float4 s = make_float4(0.f, 0.f, 0.f, 0.f);
    float4 q = make_float4(0.f, 0.f, 0.f, 0.f);
    size_t stride = (size_t)gridDim.x * blockDim.x;
    for (size_t i = (size_t)blockIdx.x * blockDim.x + tid; i < NVEC; i += stride) {
        float4 v = xv[i];
        s.x += v.x; s.y += v.y; s.z += v.z; s.w += v.w;
        q.x += v.x * v.x; q.y += v.y * v.y; q.z += v.z * v.z; q.w += v.w * v.w;

        size_t pix = i >> 4;
        int n   = (int)(pix / HW_);
        int rem = (int)(pix % HW_);
        int h   = rem / W_;
        int w   = rem % W_;
        unsigned short h0 = f2h(v.x), h1 = f2h(v.y), h2 = f2h(v.z), h3 = f2h(v.w);
        size_t dpix = ((size_t)n * HP + (h + 1)) * WP + (w + 1);
        of[dpix * 16 + g] = make_uint2((uint32_t)h0 | ((uint32_t)h1 << 16),
                                       (uint32_t)h2 | ((uint32_t)h3 << 16));
    }
    atomicAdd(&ssum[g * 4 + 0], s.x); atomicAdd(&ssq[g * 4 + 0], q.x);
    atomicAdd(&ssum[g * 4 + 1], s.y); atomicAdd(&ssq[g * 4 + 1], q.y);
    atomicAdd(&ssum[g * 4 + 2], s.z); atomicAdd(&ssq[g * 4 + 2], q.z);
    atomicAdd(&ssum[g * 4 + 3], s.w); atomicAdd(&ssq[g * 4 + 3], q.w);
    __syncthreads();
    if (tid < C_) {
        g_psum[blockIdx.x * C_ + tid] = ssum[tid];
        g_psq [blockIdx.x * C_ + tid] = ssq[tid];
    }
}

// ---------------------------------------------------------------------------
// Launch 1: PARALLEL reduce partials -> scale/shift/border + bias. 512 thr.
__global__ void __launch_bounds__(512) k_finprep(const float* __restrict__ beta,
                                                 const float* __restrict__ kw) {
    __shared__ float rs[C_ * 8];
    __shared__ float rq[C_ * 8];
    int tid = threadIdx.x;               // 512 = 64 channels x 8 slices
    int c = tid >> 3;
    int k = tid & 7;
    float s = 0.0f, q = 0.0f;
    for (int b = k; b < SBLK; b += 8) {
        s += g_psum[b * C_ + c];
        q += g_psq [b * C_ + c];
    }
    rs[tid] = s; rq[tid] = q;
    __syncthreads();
    if (tid < C_) {
        float ts = 0.0f, tq = 0.0f;
        #pragma unroll
        for (int i = 0; i < 8; i++) { ts += rs[tid * 8 + i]; tq += rq[tid * 8 + i]; }
        const float inv_m = 1.0f / (float)M_CNT;
        float m  = ts * inv_m;
        float v  = tq * inv_m - m * m;
        float sc = rsqrtf(v + 1e-5f);
        float sh = beta[tid] - m * sc;
        g_scale[tid] = sc;
        g_shift[tid] = sh;
        g_bord[tid]  = f2h(-sh / sc);
    }
    __syncthreads();
    // bias[co] = sum_{t,ci} w * shift[ci]; 8 threads per co, each 72 terms
    {
        float acc = 0.0f;
        for (int t = k; t < 9; t += 8)      // k<8 -> t in {k, k+8<9?}
            for (int ci = 0; ci < 64; ci++)
                acc += kw[((size_t)t * 64 + ci) * 64 + c] * g_shift[ci];
        rs[tid] = acc;
    }
    __syncthreads();
    if (tid < C_) {
        float a = 0.0f;
        #pragma unroll
        for (int i = 0; i < 8; i++) a += rs[tid * 8 + i];
        g_bias[tid] = a;
    }
}

// ---------------------------------------------------------------------------
// Launch 2: swizzled B image + border fill.
__global__ void __launch_bounds__(256) k_bw(const float* __restrict__ kw) {
    int i = blockIdx.x * blockDim.x + threadIdx.x;
    if (i < 36864) {
        int cout = i & 63;
        int cin  = (i >> 6) & 63;
        int t    = i >> 12;            // dy*3+dx
        int dy = t / 3, dx = t % 3;
        float v = kw[((size_t)t * 64 + cin) * 64 + cout] * g_scale[cin];
        int kk = dx * 64 + cin;
        int off = kk * BROWB + cout * 2;
        off ^= (kk & 7) << 4;
        *(unsigned short*)((char*)g_wb + (size_t)dy * BCHUNKB + off) = f2h(v);
        return;
    }
    int idx = i - 36864;
    if (idx >= 64 * 452 * 16) return;
    int g   = idx & 15;
    int bp  = (idx >> 4) % 452;
    int img = (idx >> 4) / 452;
    int h, w;
    if (bp < 114)      { h = 0;   w = bp; }
    else if (bp < 228) { h = 113; w = bp - 114; }
    else { int j = bp - 228; h = 1 + (j >> 1); w = (j & 1) ? 113 : 0; }
    const unsigned short* bd = g_bord;
    uint32_t v0 = (uint32_t)bd[g*4+0] | ((uint32_t)bd[g*4+1] << 16);
    uint32_t v1 = (uint32_t)bd[g*4+2] | ((uint32_t)bd[g*4+3] << 16);
    ((uint2*)g_xf)[(((size_t)img * HP + h) * WP + w) * 16 + g] = make_uint2(v0, v1);
}

// ---------------------------------------------------------------------------
// Launch 3 (profiled): conv. 512 thr = 16 warps = 8 pairs; warp tile 16x32.
__global__ void __launch_bounds__(512, 1)
k_conv(float* __restrict__ out) {
    extern __shared__ __align__(1024) unsigned char smem[];
    uint32_t sb = smem_to_u32(smem);
    int tid = threadIdx.x;

    // stage B once (73728 B, pre-swizzled image)
    {
        const uint4* src = (const uint4*)g_wb;
        uint4* dst = (uint4*)smem;
        for (int i = tid; i < B_BYTES / 16; i += 512) dst[i] = src[i];
    }
    __syncthreads();

    int lane = tid & 31;
    int wid  = tid >> 5;           // 0..15
    int pr   = wid >> 1;           // pair 0..7 -> pixels pr*16..+16
    int nw   = wid & 1;            // n-half: couts nw*32..+32
    int sel  = lane >> 3;
    int l7   = lane & 7;
    int barid = pr + 1;

    uint32_t apbase = sb + SM_A0 + (uint32_t)pr * (2 * AWBUF);
    uint32_t a_off  = (uint32_t)(((sel & 1) * 8 + l7) * APITCH + (sel >> 1) * 16);

    // B per-lane: row term + 2 swizzled cout-block byte offsets
    uint32_t b_lane = sb + (uint32_t)(((sel & 1) * 8 + l7) * BROWB);
    uint32_t bo0 = (uint32_t)((((sel >> 1) * 16) + nw * 64)      ^ (l7 << 4));
    uint32_t bo1 = (uint32_t)((((sel >> 1) * 16) + nw * 64 + 32) ^ (l7 << 4));

    // staging: 64 threads/pair; thread pt covers pixel pt>>2, quarter pt&3 (96B)
    int pt = tid & 63;
    uint32_t dst_off = (uint32_t)((pt >> 2) * APITCH + (pt & 3) * 96);
    uint32_t src_off = (uint32_t)((pt & 3) * 96);
    const char* gx = (const char*)g_xf;

    int cq = lane & 3;
    float bia0[4], bia1[4];
    #pragma unroll
    for (int nf = 0; nf < 4; nf++) {
        bia0[nf] = g_bias[nw * 32 + nf * 8 + 2 * cq];
        bia1[nf] = g_bias[nw * 32 + nf * 8 + 2 * cq + 1];
    }

    uint32_t jj = 0;               // free-running chunk counter (buffer parity)

    // prologue: prefetch (first tile, dy=0) into buf 0
    {
        int gp  = blockIdx.x * 128 + pr * 16 + (pt >> 2);
        int n   = gp / HW_;
        int rem = gp % HW_;
        int h   = rem / W_;
        int w   = rem % W_;
        const char* src = gx + (((size_t)n * HP + h) * WP + w) * PIXB + src_off;
        uint32_t d = apbase + dst_off;
        #pragma unroll
        for (int i = 0; i < 6; i++) CP_ASYNC16(d + i * 16, src + i * 16);
        CP_COMMIT();
    }

    for (int tile = blockIdx.x; tile < NTILES; tile += gridDim.x) {
        int gp  = tile * 128 + pr * 16 + (pt >> 2);
        int n   = gp / HW_;
        int rem = gp % HW_;
        int h   = rem / W_;
        int w   = rem % W_;
        const char* base = gx + (((size_t)n * HP + h) * WP + w) * PIXB + src_off;

        float c[16];
        #pragma unroll
        for (int i = 0; i < 16; i++) c[i] = 0.0f;

        #pragma unroll 1
        for (int j = 0; j < 3; j++) {
            uint32_t buf  = jj & 1;
            uint32_t nbuf = buf ^ 1;
            jj++;

            // 1) chunk data landed; 2) both warps of pair done reading nbuf
            CP_WAIT0();
            BAR_SYNC(barid);

            // 3) prefetch next chunk into nbuf (overlaps MMA loop below)
            if (j < 2) {
                const char* src = base + (size_t)(j + 1) * ROWB;
                uint32_t d = apbase + nbuf * AWBUF + dst_off;
                #pragma unroll
                for (int i = 0; i < 6; i++) CP_ASYNC16(d + i * 16, src + i * 16);
                CP_COMMIT();
            } else {
                int t2 = tile + gridDim.x;
                if (t2 < NTILES) {
                    int gp2  = t2 * 128 + pr * 16 + (pt >> 2);
                    int n2   = gp2 / HW_;
                    int rem2 = gp2 % HW_;
                    int h2   = rem2 / W_;
                    int w2   = rem2 % W_;
                    const char* src = gx + (((size_t)n2 * HP + h2) * WP + w2) * PIXB + src_off;
                    uint32_t d = apbase + nbuf * AWBUF + dst_off;
                    #pragma unroll
                    for (int i = 0; i < 6; i++) CP_ASYNC16(d + i * 16, src + i * 16);
                    CP_COMMIT();
                }
            }

            uint32_t Abase = apbase + buf * AWBUF + a_off;
            uint32_t Bbase = b_lane + (uint32_t)j * BCHUNKB;

            #pragma unroll
            for (int s = 0; s < 12; s++) {
                uint32_t ra[4], rb0[4], rb1[4];
                LDSM_X4(ra, Abase + s * 32);
                uint32_t Bs = Bbase + (uint32_t)s * (16 * BROWB);
                LDSM_X4_T(rb0, Bs + bo0);
                LDSM_X4_T(rb1, Bs + bo1);

                MMA16816(c +  0, ra, rb0[0], rb0[1]);
                MMA16816(c +  4, ra, rb0[2], rb0[3]);
                MMA16816(c +  8, ra, rb1[0], rb1[1]);
                MMA16816(c + 12, ra, rb1[2], rb1[3]);
            }
        }

        // epilogue: add bias, store 16 pixels x 32 couts
        int r = lane >> 2;
        int pix0 = tile * 128 + pr * 16 + r;
        float* o0 = out + (size_t)pix0 * 64 + nw * 32 + 2 * cq;
        float* o1 = o0 + 8 * 64;
        #pragma unroll
        for (int nf = 0; nf < 4; nf++) {
            *(float2*)(o0 + nf * 8) = make_float2(c[nf*4 + 0] + bia0[nf],
                                                  c[nf*4 + 1] + bia1[nf]);
            *(float2*)(o1 + nf * 8) = make_float2(c[nf*4 + 2] + bia0[nf],
                                                  c[nf*4 + 3] + bia1[nf]);
        }
    }
}

// ---------------------------------------------------------------------------
extern "C" void kernel_launch(void* const* d_in, const int* in_sizes, int n_in,
                              void* d_out, int out_size) {
    const float* x    = (const float*)d_in[0];
    const float* kw   = (const float*)d_in[1];
    const float* beta = (const float*)d_in[2];
    float* out = (float*)d_out;
    (void)in_sizes; (void)n_in; (void)out_size;

    cudaFuncSetAttribute(k_conv, cudaFuncAttributeMaxDynamicSharedMemorySize, CONV_SMEM);

    k_stats_conv<<<SBLK, 256>>>(x);                              // launch 0
    k_finprep<<<1, 512>>>(beta, kw);                             // launch 1
    k_bw<<<(36864 + 64 * 452 * 16 + 255) / 256, 256>>>(kw);      // launch 2
    k_conv<<<152, 512, CONV_SMEM>>>(out);                        // launch 3 (profiled)
}

// round 12
// speedup vs baseline: 1.1450x; 1.0171x over previous
#include <cuda_runtime.h>
#include <cuda_fp16.h>
#include <cstdint>

// ============================================================================
// x (64,112,112,64) f32 NHWC; kernels (3,3,64,64) f32 HWIO (+-1); beta (64).
// out = conv3x3_SAME(BN_train(x), kernels), fp32.
//
// BN folded into GEMM: out = conv(fp16(x_raw), w*s_ci) + bias_co; padded
// border = fp16(-shift/scale). Implicit GEMM mma.sync.m16n8k16.f16.
// Conv: persistent CTAs, 768 thr = 24 warps = 12 pairs (6 warps/SMSP).
// Pair shares a 16-pixel A buffer (double buffered, cp.async); warp tile
// 16 px x 32 co (84 regs -> fits 768-thread register file). CTA tile 192 px.
// ============================================================================

#define N_  64
#define H_  112
#define W_  112
#define C_  64
#define HP  114
#define WP  114
#define M_CNT (N_*H_*W_)
#define NVEC  ((size_t)M_CNT * 16)
#define NPIX  (N_*H_*W_)
#define HW_   (H_*W_)                // 12544
#define PIXB  (C_*2)                 // 128 B per padded pixel
#define ROWB  (WP*PIXB)              // 14592 B per padded row
#define SBLK  1024                   // stats blocks

#define CTATILE 192
#define NTILES2 ((NPIX + CTATILE - 1) / CTATILE)   // 4182 (last tile 64 px)

// B: [3 dy][192 k][64 co] fp16, 128B rows, XOR swizzle (k&7)<<4
#define BROWB  128
#define BCHUNKB (192*BROWB)          // 24576
#define B_BYTES (3*BCHUNKB)          // 73728

// A: per-PAIR [16 pixels][192 k] fp16, pitch 400B, double buffered
#define APITCH 400
#define AWBUF  (16*APITCH)           // 6400
#define SM_A0  B_BYTES
#define CONV_SMEM (B_BYTES + 12*2*AWBUF)   // 227328

// ---------------- persistent device scratch (zero-init .bss) ----------------
__device__ __align__(16) unsigned short g_xf[(size_t)N_ * HP * WP * C_];
__device__ __align__(16) unsigned short g_wb[3 * 192 * 64];
__device__ float g_psum[SBLK * C_];
__device__ float g_psq[SBLK * C_];
__device__ float g_scale[C_];
__device__ float g_shift[C_];
__device__ float g_bias[C_];
__device__ unsigned short g_bord[C_];

// ============================ PTX helpers ===================================
__device__ __forceinline__ uint32_t smem_to_u32(const void* p) {
    uint32_t a;
    asm("{ .reg .u64 t; cvta.to.shared.u64 t, %1; cvt.u32.u64 %0, t; }"
        : "=r"(a) : "l"(p));
    return a;
}

#define LDSM_X4(r, addr) \
    asm volatile("ldmatrix.sync.aligned.m8n8.x4.shared.b16 {%0,%1,%2,%3}, [%4];" \
        : "=r"((r)[0]), "=r"((r)[1]), "=r"((r)[2]), "=r"((r)[3]) : "r"(addr))

#define LDSM_X4_T(r, addr) \
    asm volatile("ldmatrix.sync.aligned.m8n8.x4.trans.shared.b16 {%0,%1,%2,%3}, [%4];" \
        : "=r"((r)[0]), "=r"((r)[1]), "=r"((r)[2]), "=r"((r)[3]) : "r"(addr))

#define MMA16816(c, a, b0v, b1v) \
    asm volatile("mma.sync.aligned.m16n8k16.row.col.f32.f16.f16.f32 " \
        "{%0,%1,%2,%3}, {%4,%5,%6,%7}, {%8,%9}, {%0,%1,%2,%3};" \
        : "+f"((c)[0]), "+f"((c)[1]), "+f"((c)[2]), "+f"((c)[3]) \
        : "r"((a)[0]), "r"((a)[1]), "r"((a)[2]), "r"((a)[3]), \
          "r"(b0v), "r"(b1v))

#define CP_ASYNC16(dst_s, src_g) \
    asm volatile("cp.async.cg.shared.global [%0], [%1], 16;" \
        :: "r"(dst_s), "l"(src_g))
#define CP_COMMIT() asm volatile("cp.async.commit_group;" ::: "memory")
#define CP_WAIT0()  asm volatile("cp.async.wait_group 0;" ::: "memory")
#define BAR_SYNC(id) asm volatile("bar.sync %0, 64;" :: "r"(id) : "memory")

__device__ __forceinline__ unsigned short f2h(float f) {
    __half h = __float2half_rn(f);
    return *reinterpret_cast<unsigned short*>(&h);
}

// ---------------------------------------------------------------------------
// Launch 0: per-channel partial moments (per-block) + raw-x fp16 conversion.
__global__ void __launch_bounds__(256) k_stats_conv(const float* __restrict__ x) {
    __shared__ float ssum[C_];
    __shared__ float ssq[C_];
    int tid = threadIdx.x;
    if (tid < C_) { ssum[tid] = 0.0f; ssq[tid] = 0.0f; }
    __syncthreads();

    const float4* xv = (const float4*)x;
    uint2* of = (uint2*)g_xf;
    int g = tid & 15;
    float4 s = make_float4(0.f, 0.f, 0.f, 0.f);
    float4 q = make_float4(0.f, 0.f, 0.f, 0.f);
    size_t stride = (size_t)gridDim.x * blockDim.x;
    for (size_t i = (size_t)blockIdx.x * blockDim.x + tid; i < NVEC; i += stride) {
        float4 v = xv[i];
        s.x += v.x; s.y += v.y; s.z += v.z; s.w += v.w;
        q.x += v.x * v.x; q.y += v.y * v.y; q.z += v.z * v.z; q.w += v.w * v.w;

        size_t pix = i >> 4;
        int n   = (int)(pix / HW_);
        int rem = (int)(pix % HW_);
        int h   = rem / W_;
        int w   = rem % W_;
        unsigned short h0 = f2h(v.x), h1 = f2h(v.y), h2 = f2h(v.z), h3 = f2h(v.w);
        size_t dpix = ((size_t)n * HP + (h + 1)) * WP + (w + 1);
        of[dpix * 16 + g] = make_uint2((uint32_t)h0 | ((uint32_t)h1 << 16),
                                       (uint32_t)h2 | ((uint32_t)h3 << 16));
    }
    atomicAdd(&ssum[g * 4 + 0], s.x); atomicAdd(&ssq[g * 4 + 0], q.x);
    atomicAdd(&ssum[g * 4 + 1], s.y); atomicAdd(&ssq[g * 4 + 1], q.y);
    atomicAdd(&ssum[g * 4 + 2], s.z); atomicAdd(&ssq[g * 4 + 2], q.z);
    atomicAdd(&ssum[g * 4 + 3], s.w); atomicAdd(&ssq[g * 4 + 3], q.w);
    __syncthreads();
    if (tid < C_) {
        g_psum[blockIdx.x * C_ + tid] = ssum[tid];
        g_psq [blockIdx.x * C_ + tid] = ssq[tid];
    }
}

// ---------------------------------------------------------------------------
// Launch 1: parallel reduce partials -> scale/shift/border + bias. 512 thr.
__global__ void __launch_bounds__(512) k_finprep(const float* __restrict__ beta,
                                                 const float* __restrict__ kw) {
    __shared__ float rs[C_ * 8];
    __shared__ float rq[C_ * 8];
    int tid = threadIdx.x;               // 512 = 64 channels x 8 slices
    int c = tid >> 3;
    int k = tid & 7;
    float s = 0.0f, q = 0.0f;
    for (int b = k; b < SBLK; b += 8) {
        s += g_psum[b * C_ + c];
        q += g_psq [b * C_ + c];
    }
    rs[tid] = s; rq[tid] = q;
    __syncthreads();
    if (tid < C_) {
        float ts = 0.0f, tq = 0.0f;
        #pragma unroll
        for (int i = 0; i < 8; i++) { ts += rs[tid * 8 + i]; tq += rq[tid * 8 + i]; }
        const float inv_m = 1.0f / (float)M_CNT;
        float m  = ts * inv_m;
        float v  = tq * inv_m - m * m;
        float sc = rsqrtf(v + 1e-5f);
        float sh = beta[tid] - m * sc;
        g_scale[tid] = sc;
        g_shift[tid] = sh;
        g_bord[tid]  = f2h(-sh / sc);
    }
    __syncthreads();
    {
        float acc = 0.0f;
        for (int t = k; t < 9; t += 8)
            for (int ci = 0; ci < 64; ci++)
                acc += kw[((size_t)t * 64 + ci) * 64 + c] * g_shift[ci];
        rs[tid] = acc;
    }
    __syncthreads();
    if (tid < C_) {
        float a = 0.0f;
        #pragma unroll
        for (int i = 0; i < 8; i++) a += rs[tid * 8 + i];
        g_bias[tid] = a;
    }
}

// ---------------------------------------------------------------------------
// Launch 2: swizzled B image + border fill.
__global__ void __launch_bounds__(256) k_bw(const float* __restrict__ kw) {
    int i = blockIdx.x * blockDim.x + threadIdx.x;
    if (i < 36864) {
        int cout = i & 63;
        int cin  = (i >> 6) & 63;
        int t    = i >> 12;            // dy*3+dx
        int dy = t / 3, dx = t % 3;
        float v = kw[((size_t)t * 64 + cin) * 64 + cout] * g_scale[cin];
        int kk = dx * 64 + cin;
        int off = kk * BROWB + cout * 2;
        off ^= (kk & 7) << 4;
        *(unsigned short*)((char*)g_wb + (size_t)dy * BCHUNKB + off) = f2h(v);
        return;
    }
    int idx = i - 36864;
    if (idx >= 64 * 452 * 16) return;
    int g   = idx & 15;
    int bp  = (idx >> 4) % 452;
    int img = (idx >> 4) / 452;
    int h, w;
    if (bp < 114)      { h = 0;   w = bp; }
    else if (bp < 228) { h = 113; w = bp - 114; }
    else { int j = bp - 228; h = 1 + (j >> 1); w = (j & 1) ? 113 : 0; }
    const unsigned short* bd = g_bord;
    uint32_t v0 = (uint32_t)bd[g*4+0] | ((uint32_t)bd[g*4+1] << 16);
    uint32_t v1 = (uint32_t)bd[g*4+2] | ((uint32_t)bd[g*4+3] << 16);
    ((uint2*)g_xf)[(((size_t)img * HP + h) * WP + w) * 16 + g] = make_uint2(v0, v1);
}

// ---------------------------------------------------------------------------
// Launch 3 (profiled): conv. 768 thr = 24 warps = 12 pairs; warp tile 16x32.
// CTA tile 192 px; last tile partial (loads clamped, stores predicated).
__global__ void __launch_bounds__(768, 1)
k_conv(float* __restrict__ out) {
    extern __shared__ __align__(1024) unsigned char smem[];
    uint32_t sb = smem_to_u32(smem);
    int tid = threadIdx.x;

    // stage B once (pre-swizzled image)
    {
        const uint4* src = (const uint4*)g_wb;
        uint4* dst = (uint4*)smem;
        for (int i = tid; i < B_BYTES / 16; i += 768) dst[i] = src[i];
    }
    __syncthreads();

    int lane = tid & 31;
    int wid  = tid >> 5;           // 0..23
    int pr   = wid >> 1;           // pair 0..11 -> pixels pr*16..+16
    int nw   = wid & 1;            // n-half: couts nw*32..+32
    int sel  = lane >> 3;
    int l7   = lane & 7;
    int barid = pr + 1;            // named barriers 1..12

    uint32_t apbase = sb + SM_A0 + (uint32_t)pr * (2 * AWBUF);
    uint32_t a_off  = (uint32_t)(((sel & 1) * 8 + l7) * APITCH + (sel >> 1) * 16);

    uint32_t b_lane = sb + (uint32_t)(((sel & 1) * 8 + l7) * BROWB);
    uint32_t bo0 = (uint32_t)((((sel >> 1) * 16) + nw * 64)      ^ (l7 << 4));
    uint32_t bo1 = (uint32_t)((((sel >> 1) * 16) + nw * 64 + 32) ^ (l7 << 4));

    // staging: 64 threads/pair; thread pt covers pixel pt>>2, quarter pt&3
    int pt = tid & 63;
    uint32_t dst_off = (uint32_t)((pt >> 2) * APITCH + (pt & 3) * 96);
    uint32_t src_off = (uint32_t)((pt & 3) * 96);
    const char* gx = (const char*)g_xf;

    int cq = lane & 3;
    float bia0[4], bia1[4];
    #pragma unroll
    for (int nf = 0; nf < 4; nf++) {
        bia0[nf] = g_bias[nw * 32 + nf * 8 + 2 * cq];
        bia1[nf] = g_bias[nw * 32 + nf * 8 + 2 * cq + 1];
    }

    uint32_t jj = 0;

    // prologue: prefetch (first tile, dy=0) into buf 0
    {
        int gp  = blockIdx.x * CTATILE + pr * 16 + (pt >> 2);
        if (gp >= NPIX) gp = NPIX - 1;
        int n   = gp / HW_;
        int rem = gp % HW_;
        int h   = rem / W_;
        int w   = rem % W_;
        const char* src = gx + (((size_t)n * HP + h) * WP + w) * PIXB + src_off;
        uint32_t d = apbase + dst_off;
        #pragma unroll
        for (int i = 0; i < 6; i++) CP_ASYNC16(d + i * 16, src + i * 16);
        CP_COMMIT();
    }

    for (int tile = blockIdx.x; tile < NTILES2; tile += gridDim.x) {
        int gp  = tile * CTATILE + pr * 16 + (pt >> 2);
        if (gp >= NPIX) gp = NPIX - 1;
        int n   = gp / HW_;
        int rem = gp % HW_;
        int h   = rem / W_;
        int w   = rem % W_;
        const char* base = gx + (((size_t)n * HP + h) * WP + w) * PIXB + src_off;

        float c[16];
        #pragma unroll
        for (int i = 0; i < 16; i++) c[i] = 0.0f;

        #pragma unroll 1
        for (int j = 0; j < 3; j++) {
            uint32_t buf  = jj & 1;
            uint32_t nbuf = buf ^ 1;
            jj++;

            // 1) chunk data landed; 2) both warps of pair done reading nbuf
            CP_WAIT0();
            BAR_SYNC(barid);

            // 3) prefetch next chunk into nbuf (overlaps MMA loop below)
            if (j < 2) {
                const char* src = base + (size_t)(j + 1) * ROWB;
                uint32_t d = apbase + nbuf * AWBUF + dst_off;
                #pragma unroll
                for (int i = 0; i < 6; i++) CP_ASYNC16(d + i * 16, src + i * 16);
                CP_COMMIT();
            } else {
                int t2 = tile + gridDim.x;
                if (t2 < NTILES2) {
                    int gp2  = t2 * CTATILE + pr * 16 + (pt >> 2);
                    if (gp2 >= NPIX) gp2 = NPIX - 1;
                    int n2   = gp2 / HW_;
                    int rem2 = gp2 % HW_;
                    int h2   = rem2 / W_;
                    int w2   = rem2 % W_;
                    const char* src = gx + (((size_t)n2 * HP + h2) * WP + w2) * PIXB + src_off;
                    uint32_t d = apbase + nbuf * AWBUF + dst_off;
                    #pragma unroll
                    for (int i = 0; i < 6; i++) CP_ASYNC16(d + i * 16, src + i * 16);
                    CP_COMMIT();
                }
            }

            uint32_t Abase = apbase + buf * AWBUF + a_off;
            uint32_t Bbase = b_lane + (uint32_t)j * BCHUNKB;

            #pragma unroll
            for (int s = 0; s < 12; s++) {
                uint32_t ra[4], rb0[4], rb1[4];
                LDSM_X4(ra, Abase + s * 32);
                uint32_t Bs = Bbase + (uint32_t)s * (16 * BROWB);
                LDSM_X4_T(rb0, Bs + bo0);
                LDSM_X4_T(rb1, Bs + bo1);

                MMA16816(c +  0, ra, rb0[0], rb0[1]);
                MMA16816(c +  4, ra, rb0[2], rb0[3]);
                MMA16816(c +  8, ra, rb1[0], rb1[1]);
                MMA16816(c + 12, ra, rb1[2], rb1[3]);
            }
        }

        // epilogue: add bias, store 16 pixels x 32 couts (predicated for tail)
        int r = lane >> 2;
        int pix0 = tile * CTATILE + pr * 16 + r;
        float* o0 = out + (size_t)pix0 * 64 + nw * 32 + 2 * cq;
        float* o1 = o0 + 8 * 64;
        if (pix0 < NPIX) {
            #pragma unroll
            for (int nf = 0; nf < 4; nf++)
                *(float2*)(o0 + nf * 8) = make_float2(c[nf*4 + 0] + bia0[nf],
                                                      c[nf*4 + 1] + bia1[nf]);
        }
        if (pix0 + 8 < NPIX) {
            #pragma unroll
            for (int nf = 0; nf < 4; nf++)
                *(float2*)(o1 + nf * 8) = make_float2(c[nf*4 + 2] + bia0[nf],
                                                      c[nf*4 + 3] + bia1[nf]);
        }
    }
}

// ---------------------------------------------------------------------------
extern "C" void kernel_launch(void* const* d_in, const int* in_sizes, int n_in,
                              void* d_out, int out_size) {
    const float* x    = (const float*)d_in[0];
    const float* kw   = (const float*)d_in[1];
    const float* beta = (const float*)d_in[2];
    float* out = (float*)d_out;
    (void)in_sizes; (void)n_in; (void)out_size;

    cudaFuncSetAttribute(k_conv, cudaFuncAttributeMaxDynamicSharedMemorySize, CONV_SMEM);

    k_stats_conv<<<SBLK, 256>>>(x);                              // launch 0
    k_finprep<<<1, 512>>>(beta, kw);                             // launch 1
    k_bw<<<(36864 + 64 * 452 * 16 + 255) / 256, 256>>>(kw);      // launch 2
    k_conv<<<152, 768, CONV_SMEM>>>(out);                        // launch 3 (profiled)
}